// round 14
// baseline (speedup 1.0000x reference)
#include <cuda_runtime.h>
#include <cuda_fp16.h>
#include <math.h>
#include <stdint.h>

#define SEQ 1024
#define HID 4096
#define NH  64
#define HD  64
#define SZ  (SEQ*HID)

__device__ float   g_kvrg[4*SZ];     // k,v,r,g fp32
__device__ float   g_osum[SZ];       // WKV output (dgroup-reduced) fp32
__device__ __half  g_mA[4*SZ];       // mixed activations fp16 (RN)
__device__ __half  g_ab[SZ];         // normed/gated fp16

__device__ __forceinline__ uint32_t pkh(__half a, __half b){
    __half2 t = __halves2half2(a, b);
    return *reinterpret_cast<uint32_t*>(&t);
}
__device__ __forceinline__ float silu(float x){ return x / (1.f + expf(-x)); }
__device__ __forceinline__ uint32_t smem_u32(const void* p){
    uint32_t a;
    asm("{ .reg .u64 t; cvta.to.shared.u64 t, %1; cvt.u32.u64 %0, t; }" : "=r"(a) : "l"(p));
    return a;
}
__device__ __forceinline__ void mma16816(float* c, const uint32_t* a, uint32_t b0, uint32_t b1){
    asm volatile("mma.sync.aligned.m16n8k16.row.col.f32.f16.f16.f32 "
        "{%0,%1,%2,%3}, {%4,%5,%6,%7}, {%8,%9}, {%0,%1,%2,%3};"
        : "+f"(c[0]), "+f"(c[1]), "+f"(c[2]), "+f"(c[3])
        : "r"(a[0]), "r"(a[1]), "r"(a[2]), "r"(a[3]), "r"(b0), "r"(b1));
}
__device__ __forceinline__ void ldsm4(uint32_t* r, uint32_t a){
    asm volatile("ldmatrix.sync.aligned.m8n8.x4.shared.b16 {%0,%1,%2,%3}, [%4];"
        : "=r"(r[0]), "=r"(r[1]), "=r"(r[2]), "=r"(r[3]) : "r"(a));
}
__device__ __forceinline__ void ldsm2(uint32_t* r, uint32_t a){
    asm volatile("ldmatrix.sync.aligned.m8n8.x2.shared.b16 {%0,%1}, [%2];"
        : "=r"(r[0]), "=r"(r[1]) : "r"(a));
}
__device__ __forceinline__ void cpa16(uint32_t dst, const void* src){
    asm volatile("cp.async.cg.shared.global [%0], [%1], 16;" :: "r"(dst), "l"(src));
}
#define CPA_COMMIT() asm volatile("cp.async.commit_group;" ::: "memory")
#define CPA_WAIT1()  asm volatile("cp.async.wait_group 1;" ::: "memory")

// ---------------- activation prepass: mix -> fp16 (RN) ----------------------
__global__ __launch_bounds__(256) void prepass_kernel(
    const float* __restrict__ hidden, const float* __restrict__ mk,
    const float* __restrict__ mv, const float* __restrict__ mr, const float* __restrict__ mg)
{
    int idx = (blockIdx.x*256 + threadIdx.x)*4;
    int t = idx >> 12, c = idx & 4095;
    float4 hv = *(const float4*)(hidden + idx);
    float4 sv = make_float4(0.f,0.f,0.f,0.f);
    if (t > 0) sv = *(const float4*)(hidden + idx - HID);
    const float* ms[4] = {mk, mv, mr, mg};
    #pragma unroll
    for (int p = 0; p < 4; p++){
        float4 m = *(const float4*)(ms[p] + c);
        float x0 = hv.x*m.x + sv.x*(1.f-m.x), x1 = hv.y*m.y + sv.y*(1.f-m.y);
        float x2 = hv.z*m.z + sv.z*(1.f-m.z), x3 = hv.w*m.w + sv.w*(1.f-m.w);
        *(uint2*)(g_mA + (size_t)p*SZ + idx) =
            make_uint2(pkh(__float2half(x0), __float2half(x1)),
                       pkh(__float2half(x2), __float2half(x3)));
    }
}

// ---------------- mma.sync GEMM: A fp16 cp.async, B fp32 inline-convert -----
// C[M,N] = A[M,K] * W[N,K]^T.  Tile 128x128, KC=64, 8 warps (4m x 2n).
#define KC 64
#define SP 72
#define TH (128*SP)
#define NSTAGE 3
#define GSMEM (NSTAGE*2*TH*2)

__global__ __launch_bounds__(256, 2) void gemm_kernel(
    int mode, const float* __restrict__ W0, const float* __restrict__ W1,
    const float* __restrict__ W2, const float* __restrict__ W3,
    const float* __restrict__ W4, float* __restrict__ dout)
{
    extern __shared__ __half sm[];
    const int tid = threadIdx.x, z = blockIdx.z;
    const __half* AG;
    const float* BG;
    float* outp;
    bool do_silu = false;
    if (mode == 0){
        AG = g_mA + (size_t)z*SZ;
        BG = (z==0)?W0:(z==1)?W1:(z==2)?W2:W3;
        outp = g_kvrg + (size_t)z*SZ; do_silu = (z==3);
    } else {
        AG = g_ab;
        BG = W4;
        outp = dout;
    }

    const int m0 = blockIdx.x*128, n0 = blockIdx.y*128;
    const int wid = tid>>5, lane = tid&31;
    const int wm = (wid&3)*32, wn = (wid>>2)*64;
    const int r = lane>>2, q = lane&3;
    const uint32_t sbase = smem_u32(sm);

    // A copy mapping (cp.async): 32 rows x 8 segs per 256 threads
    const int crow = tid>>3, cseg = tid&7;
    const size_t gAoff = (size_t)(m0+crow)*HID + cseg*8;
    const uint32_t soff = (uint32_t)(crow*SP + cseg*8)*2;

    // B load mapping: row = tid>>1 (0..127), half = tid&1 -> 32 cols
    const int brow = tid>>1, bhalf = tid&1;
    const float* Bsrc = BG + (size_t)(n0+brow)*HID + bhalf*32;
    float4 breg[8];

    float acc[2][8][4];
    #pragma unroll
    for (int i=0;i<2;i++)
        #pragma unroll
        for (int j=0;j<8;j++)
            #pragma unroll
            for (int k=0;k<4;k++) acc[i][j][k]=0.f;

    auto issueA = [&](int c, int s){
        const int k0 = c*KC;
        const uint32_t st = sbase + (uint32_t)(s*2*TH)*2;
        #pragma unroll
        for (int i = 0; i < 4; i++)
            cpa16(st + soff + (uint32_t)(i*32*SP)*2, AG + gAoff + k0 + (size_t)i*32*HID);
    };
    auto loadB = [&](int c){
        const float* src = Bsrc + c*KC;
        #pragma unroll
        for (int j = 0; j < 8; j++) breg[j] = *(const float4*)(src + j*4);
    };
    auto storeB = [&](int s){
        __half* Bd = sm + (size_t)s*2*TH + TH + brow*SP + bhalf*32;
        #pragma unroll
        for (int jj = 0; jj < 4; jj++){
            float4 x = breg[2*jj], y = breg[2*jj+1];
            uint4 v = make_uint4(pkh(__float2half(x.x),__float2half(x.y)),
                                 pkh(__float2half(x.z),__float2half(x.w)),
                                 pkh(__float2half(y.x),__float2half(y.y)),
                                 pkh(__float2half(y.z),__float2half(y.w)));
            *(uint4*)(Bd + jj*8) = v;
        }
    };

    // prologue: B0 -> regs -> smem stage0; A0/A1 via cp.async
    loadB(0);
    issueA(0, 0); CPA_COMMIT();
    issueA(1, 1); CPA_COMMIT();
    storeB(0);

    const int NCH = HID/KC;
    for (int c = 0; c < NCH; c++){
        const int s = c % NSTAGE;
        CPA_WAIT1();
        __syncthreads();                       // A_c + B_c visible
        if (c + 2 < NCH){ issueA(c + 2, (c + 2) % NSTAGE); }
        CPA_COMMIT();
        if (c + 1 < NCH) loadB(c + 1);         // LDG overlaps compute

        const uint32_t stA = sbase + (uint32_t)(s*2*TH)*2;
        const uint32_t stB = stA + (uint32_t)TH*2;

        #pragma unroll
        for (int ko = 0; ko < 32; ko += 16){
            uint32_t aa[2][4], bb[8][2];
            const int arow = wm + (lane&15), acol = ko + (lane>>4)*8;
            #pragma unroll
            for (int fm = 0; fm < 2; fm++)
                ldsm4(aa[fm], stA + (uint32_t)((arow + fm*16)*SP + acol)*2);
            const int brw = wn + (lane&7), bcol = ko + ((lane>>3)&1)*8;
            #pragma unroll
            for (int fn = 0; fn < 8; fn++)
                ldsm2(bb[fn], stB + (uint32_t)((brw + fn*8)*SP + bcol)*2);
            #pragma unroll
            for (int fn = 0; fn < 8; fn++)
                #pragma unroll
                for (int fm = 0; fm < 2; fm++)
                    mma16816(acc[fm][fn], aa[fm], bb[fn][0], bb[fn][1]);
        }
        if (c + 1 < NCH) storeB((c + 1) % NSTAGE);   // mid-loop: regs -> next stage
        #pragma unroll
        for (int ko = 32; ko < 64; ko += 16){
            uint32_t aa[2][4], bb[8][2];
            const int arow = wm + (lane&15), acol = ko + (lane>>4)*8;
            #pragma unroll
            for (int fm = 0; fm < 2; fm++)
                ldsm4(aa[fm], stA + (uint32_t)((arow + fm*16)*SP + acol)*2);
            const int brw = wn + (lane&7), bcol = ko + ((lane>>3)&1)*8;
            #pragma unroll
            for (int fn = 0; fn < 8; fn++)
                ldsm2(bb[fn], stB + (uint32_t)((brw + fn*8)*SP + bcol)*2);
            #pragma unroll
            for (int fn = 0; fn < 8; fn++)
                #pragma unroll
                for (int fm = 0; fm < 2; fm++)
                    mma16816(acc[fm][fn], aa[fm], bb[fn][0], bb[fn][1]);
        }
        __syncthreads();
    }

    #pragma unroll
    for (int fm = 0; fm < 2; fm++){
        #pragma unroll
        for (int fn = 0; fn < 8; fn++){
            int row0 = m0 + wm + fm*16 + r;
            int col  = n0 + wn + fn*8 + q*2;
            float2 v0 = make_float2(acc[fm][fn][0], acc[fm][fn][1]);
            float2 v1 = make_float2(acc[fm][fn][2], acc[fm][fn][3]);
            if (do_silu){
                v0.x = silu(v0.x); v0.y = silu(v0.y);
                v1.x = silu(v1.x); v1.y = silu(v1.y);
            }
            *(float2*)(outp + (size_t)row0*HID + col)     = v0;
            *(float2*)(outp + (size_t)(row0+8)*HID + col) = v1;
        }
    }
}

// ---------------- WKV recurrence: 512 thr, in-smem dgroup reduction ---------
__global__ __launch_bounds__(512) void wkv_kernel(
    const float* __restrict__ time_decay, const float* __restrict__ time_faaaa)
{
    const int head = blockIdx.x, ehalf = blockIdx.y;
    const int tid = threadIdx.x, eg = tid & 31, dg = tid >> 5;
    __shared__ float ks[16][64], rs[16][64], vs[16][32];
    __shared__ float sop[16][16][33];

    float td[4], tf[4], st[4];
    #pragma unroll
    for (int j = 0; j < 4; j++){
        int d = dg*4 + j;
        td[j] = expf(-expf(time_decay[head*HD + d]));
        tf[j] = time_faaaa[head*HD + d];
        st[j] = 0.f;
    }
    const float* kb = g_kvrg + 0*(size_t)SZ + head*HD;
    const float* vb = g_kvrg + 1*(size_t)SZ + head*HD + ehalf*32;
    const float* rb = g_kvrg + 2*(size_t)SZ + head*HD;
    float* op = g_osum + head*HD + ehalf*32;

    const int krow = (tid & 255) >> 4, kseg = tid & 15;
    const int vrow = tid >> 3, vseg = tid & 7;
    float4 kra, va;
    if (tid < 256) kra = *(const float4*)(kb + (size_t)krow*HID + kseg*4);
    else           kra = *(const float4*)(rb + (size_t)krow*HID + kseg*4);
    if (tid < 128) va  = *(const float4*)(vb + (size_t)vrow*HID + vseg*4);

    const int rtt = tid >> 5;
    for (int c = 0; c < SEQ/16; c++){
        if (tid < 256) *(float4*)&ks[krow][kseg*4] = kra;
        else           *(float4*)&rs[krow][kseg*4] = kra;
        if (tid < 128) *(float4*)&vs[vrow][vseg*4] = va;
        __syncthreads();
        if (c < SEQ/16 - 1){
            const size_t t1 = (size_t)(c+1)*16;
            if (tid < 256) kra = *(const float4*)(kb + (t1+krow)*HID + kseg*4);
            else           kra = *(const float4*)(rb + (t1+krow)*HID + kseg*4);
            if (tid < 128) va  = *(const float4*)(vb + (t1+vrow)*HID + vseg*4);
        }
        #pragma unroll
        for (int tt = 0; tt < 16; tt++){
            const float ve = vs[tt][eg];
            float4 k4 = *(const float4*)&ks[tt][dg*4];
            float4 r4 = *(const float4*)&rs[tt][dg*4];
            float kv, o0, o1;
            kv = k4.x*ve; o0 = r4.x * fmaf(tf[0],kv,st[0]); st[0] = fmaf(td[0],st[0],kv);
            kv = k4.y*ve; o1 = r4.y * fmaf(tf[1],kv,st[1]); st[1] = fmaf(td[1],st[1],kv);
            kv = k4.z*ve; o0 = fmaf(r4.z, fmaf(tf[2],kv,st[2]), o0); st[2] = fmaf(td[2],st[2],kv);
            kv = k4.w*ve; o1 = fmaf(r4.w, fmaf(tf[3],kv,st[3]), o1); st[3] = fmaf(td[3],st[3],kv);
            sop[dg][tt][eg] = o0 + o1;
        }
        __syncthreads();
        float s = 0.f;
        #pragma unroll
        for (int d2 = 0; d2 < 16; d2++) s += sop[d2][rtt][eg];
        op[(size_t)(c*16 + rtt)*HID + eg] = s;
        __syncthreads();
    }
}

// ---------------- GroupNorm + gate -> fp16 ----------------------------------
__global__ __launch_bounds__(256) void norm_kernel(
    const float* __restrict__ gnw, const float* __restrict__ gnb)
{
    const int wid = threadIdx.x >> 5, lane = threadIdx.x & 31;
    const int g = blockIdx.x*8 + wid;
    const int t = g >> 6, h = g & 63, e0 = lane*2;
    const size_t bse = (size_t)t*HID + h*HD + e0;

    float2 ov = *(const float2*)(g_osum + bse);
    float o0 = ov.x, o1 = ov.y;
    float s = o0 + o1, s2 = o0*o0 + o1*o1;
    #pragma unroll
    for (int off = 16; off > 0; off >>= 1){
        s  += __shfl_xor_sync(0xffffffffu, s,  off);
        s2 += __shfl_xor_sync(0xffffffffu, s2, off);
    }
    const float mean = s * (1.f/64.f);
    const float var  = s2 * (1.f/64.f) - mean*mean;
    const float rstd = rsqrtf(var + 1e-5f);
    float2 gt = *(const float2*)(g_kvrg + 3*(size_t)SZ + bse);
    const float w0 = gnw[h*HD+e0], w1 = gnw[h*HD+e0+1];
    const float b0 = gnb[h*HD+e0], b1 = gnb[h*HD+e0+1];
    float y0 = ((o0-mean)*rstd*w0 + b0) * gt.x;
    float y1 = ((o1-mean)*rstd*w1 + b1) * gt.y;
    *(uint32_t*)(g_ab + bse) = pkh(__float2half(y0), __float2half(y1));
}

// ---------------------------------------------------------------------------
extern "C" void kernel_launch(void* const* d_in, const int* in_sizes, int n_in,
                              void* d_out, int out_size)
{
    const float* hidden     = (const float*)d_in[0];
    const float* w_key      = (const float*)d_in[1];
    const float* w_value    = (const float*)d_in[2];
    const float* w_recept   = (const float*)d_in[3];
    const float* w_gate     = (const float*)d_in[4];
    const float* w_output   = (const float*)d_in[5];
    const float* tm_key     = (const float*)d_in[6];
    const float* tm_value   = (const float*)d_in[7];
    const float* tm_recept  = (const float*)d_in[8];
    const float* tm_gate    = (const float*)d_in[9];
    const float* time_decay = (const float*)d_in[10];
    const float* time_faaaa = (const float*)d_in[11];
    const float* gn_w       = (const float*)d_in[12];
    const float* gn_b       = (const float*)d_in[13];

    cudaFuncSetAttribute(gemm_kernel, cudaFuncAttributeMaxDynamicSharedMemorySize, GSMEM);

    prepass_kernel<<<SZ/1024, 256>>>(hidden, tm_key, tm_value, tm_recept, tm_gate);

    dim3 gproj(SEQ/128, HID/128, 4);
    gemm_kernel<<<gproj, 256, GSMEM>>>(0, w_key, w_value, w_recept, w_gate,
                                       w_output, nullptr);

    dim3 gwkv(NH, 2);
    wkv_kernel<<<gwkv, 512>>>(time_decay, time_faaaa);

    norm_kernel<<<SEQ*NH/8, 256>>>(gn_w, gn_b);

    dim3 gout(SEQ/128, HID/128, 1);
    gemm_kernel<<<gout, 256, GSMEM>>>(1, w_key, w_value, w_recept, w_gate,
                                      w_output, (float*)d_out);
}

// round 15
// speedup vs baseline: 1.4312x; 1.4312x over previous
#include <cuda_runtime.h>
#include <cuda_fp16.h>
#include <math.h>
#include <stdint.h>

#define SEQ 1024
#define HID 4096
#define NH  64
#define HD  64
#define SZ  (SEQ*HID)

__device__ float   g_kvrg[4*SZ];     // k,v,r,g fp32
__device__ float   g_osum[SZ];       // WKV output (dgroup-reduced) fp32
__device__ __half  g_mA[4*SZ];       // mixed activations fp16 (RN)
__device__ __half  g_ab[SZ];         // normed/gated fp16

__device__ __forceinline__ uint32_t pkh(__half a, __half b){
    __half2 t = __halves2half2(a, b);
    return *reinterpret_cast<uint32_t*>(&t);
}
__device__ __forceinline__ float silu(float x){ return x / (1.f + expf(-x)); }
__device__ __forceinline__ uint32_t smem_u32(const void* p){
    uint32_t a;
    asm("{ .reg .u64 t; cvta.to.shared.u64 t, %1; cvt.u32.u64 %0, t; }" : "=r"(a) : "l"(p));
    return a;
}
__device__ __forceinline__ void mma16816(float* c, const uint32_t* a, uint32_t b0, uint32_t b1){
    asm volatile("mma.sync.aligned.m16n8k16.row.col.f32.f16.f16.f32 "
        "{%0,%1,%2,%3}, {%4,%5,%6,%7}, {%8,%9}, {%0,%1,%2,%3};"
        : "+f"(c[0]), "+f"(c[1]), "+f"(c[2]), "+f"(c[3])
        : "r"(a[0]), "r"(a[1]), "r"(a[2]), "r"(a[3]), "r"(b0), "r"(b1));
}
__device__ __forceinline__ void ldsm4(uint32_t* r, uint32_t a){
    asm volatile("ldmatrix.sync.aligned.m8n8.x4.shared.b16 {%0,%1,%2,%3}, [%4];"
        : "=r"(r[0]), "=r"(r[1]), "=r"(r[2]), "=r"(r[3]) : "r"(a));
}
__device__ __forceinline__ void ldsm2(uint32_t* r, uint32_t a){
    asm volatile("ldmatrix.sync.aligned.m8n8.x2.shared.b16 {%0,%1}, [%2];"
        : "=r"(r[0]), "=r"(r[1]) : "r"(a));
}
__device__ __forceinline__ void cpa16(uint32_t dst, const void* src){
    asm volatile("cp.async.cg.shared.global [%0], [%1], 16;" :: "r"(dst), "l"(src));
}
#define CPA_COMMIT() asm volatile("cp.async.commit_group;" ::: "memory")
#define CPA_WAIT1()  asm volatile("cp.async.wait_group 1;" ::: "memory")

// ---------------- activation prepass: mix -> fp16 (RN) ----------------------
__global__ __launch_bounds__(256) void prepass_kernel(
    const float* __restrict__ hidden, const float* __restrict__ mk,
    const float* __restrict__ mv, const float* __restrict__ mr, const float* __restrict__ mg)
{
    int idx = (blockIdx.x*256 + threadIdx.x)*4;
    int t = idx >> 12, c = idx & 4095;
    float4 hv = *(const float4*)(hidden + idx);
    float4 sv = make_float4(0.f,0.f,0.f,0.f);
    if (t > 0) sv = *(const float4*)(hidden + idx - HID);
    const float* ms[4] = {mk, mv, mr, mg};
    #pragma unroll
    for (int p = 0; p < 4; p++){
        float4 m = *(const float4*)(ms[p] + c);
        float x0 = hv.x*m.x + sv.x*(1.f-m.x), x1 = hv.y*m.y + sv.y*(1.f-m.y);
        float x2 = hv.z*m.z + sv.z*(1.f-m.z), x3 = hv.w*m.w + sv.w*(1.f-m.w);
        *(uint2*)(g_mA + (size_t)p*SZ + idx) =
            make_uint2(pkh(__float2half(x0), __float2half(x1)),
                       pkh(__float2half(x2), __float2half(x3)));
    }
}

// ---------------- mma.sync GEMM: A fp16 cp.async, B fp32 inline-convert -----
// C[M,N] = A[M,K] * W[N,K]^T.  Tile 128x128, KC=64, 8 warps (4m x 2n).
// B staged in TWO passes of breg[4] (16 regs) to stay under the 128-reg cap.
#define KC 64
#define SP 72
#define TH (128*SP)
#define NSTAGE 3
#define GSMEM (NSTAGE*2*TH*2)

__global__ __launch_bounds__(256, 2) void gemm_kernel(
    int mode, const float* __restrict__ W0, const float* __restrict__ W1,
    const float* __restrict__ W2, const float* __restrict__ W3,
    const float* __restrict__ W4, float* __restrict__ dout)
{
    extern __shared__ __half sm[];
    const int tid = threadIdx.x, z = blockIdx.z;
    const __half* AG;
    const float* BG;
    float* outp;
    bool do_silu = false;
    if (mode == 0){
        AG = g_mA + (size_t)z*SZ;
        BG = (z==0)?W0:(z==1)?W1:(z==2)?W2:W3;
        outp = g_kvrg + (size_t)z*SZ; do_silu = (z==3);
    } else {
        AG = g_ab;
        BG = W4;
        outp = dout;
    }

    const int m0 = blockIdx.x*128, n0 = blockIdx.y*128;
    const int wid = tid>>5, lane = tid&31;
    const int wm = (wid&3)*32, wn = (wid>>2)*64;
    const int r = lane>>2, q = lane&3;
    const uint32_t sbase = smem_u32(sm);

    // A copy mapping (cp.async): 32 rows x 8 segs per 256 threads
    const int crow = tid>>3, cseg = tid&7;
    const size_t gAoff = (size_t)(m0+crow)*HID + cseg*8;
    const uint32_t soff = (uint32_t)(crow*SP + cseg*8)*2;

    // B load mapping: pass p covers rows [p*64, p*64+64); row=tid>>2, cols seg*16
    const int brow = tid>>2, bseg = tid&3;
    float4 breg[4];

    float acc[2][8][4];
    #pragma unroll
    for (int i=0;i<2;i++)
        #pragma unroll
        for (int j=0;j<8;j++)
            #pragma unroll
            for (int k=0;k<4;k++) acc[i][j][k]=0.f;

    auto issueA = [&](int c, int s){
        const int k0 = c*KC;
        const uint32_t st = sbase + (uint32_t)(s*2*TH)*2;
        #pragma unroll
        for (int i = 0; i < 4; i++)
            cpa16(st + soff + (uint32_t)(i*32*SP)*2, AG + gAoff + k0 + (size_t)i*32*HID);
    };
    auto loadB = [&](int c, int p){
        const float* src = BG + (size_t)(n0 + p*64 + brow)*HID + c*KC + bseg*16;
        #pragma unroll
        for (int j = 0; j < 4; j++) breg[j] = *(const float4*)(src + j*4);
    };
    auto storeB = [&](int s, int p){
        __half* Bd = sm + (size_t)s*2*TH + TH + (p*64 + brow)*SP + bseg*16;
        #pragma unroll
        for (int jj = 0; jj < 2; jj++){
            float4 x = breg[2*jj], y = breg[2*jj+1];
            uint4 v = make_uint4(pkh(__float2half(x.x),__float2half(x.y)),
                                 pkh(__float2half(x.z),__float2half(x.w)),
                                 pkh(__float2half(y.x),__float2half(y.y)),
                                 pkh(__float2half(y.z),__float2half(y.w)));
            *(uint4*)(Bd + jj*8) = v;
        }
    };

    // prologue: B0 (both passes) -> smem stage0; A0/A1 via cp.async
    loadB(0, 0);
    issueA(0, 0); CPA_COMMIT();
    issueA(1, 1); CPA_COMMIT();
    storeB(0, 0);
    loadB(0, 1);
    storeB(0, 1);

    const int NCH = HID/KC;
    for (int c = 0; c < NCH; c++){
        const int s = c % NSTAGE;
        CPA_WAIT1();
        __syncthreads();                       // A_c + B_c visible
        if (c + 2 < NCH) issueA(c + 2, (c + 2) % NSTAGE);
        CPA_COMMIT();
        if (c + 1 < NCH) loadB(c + 1, 0);      // LDG overlaps compute

        const uint32_t stA = sbase + (uint32_t)(s*2*TH)*2;
        const uint32_t stB = stA + (uint32_t)TH*2;

        #pragma unroll
        for (int ko = 0; ko < 32; ko += 16){
            uint32_t aa[2][4], bb[8][2];
            const int arow = wm + (lane&15), acol = ko + (lane>>4)*8;
            #pragma unroll
            for (int fm = 0; fm < 2; fm++)
                ldsm4(aa[fm], stA + (uint32_t)((arow + fm*16)*SP + acol)*2);
            const int brw = wn + (lane&7), bcol = ko + ((lane>>3)&1)*8;
            #pragma unroll
            for (int fn = 0; fn < 8; fn++)
                ldsm2(bb[fn], stB + (uint32_t)((brw + fn*8)*SP + bcol)*2);
            #pragma unroll
            for (int fn = 0; fn < 8; fn++)
                #pragma unroll
                for (int fm = 0; fm < 2; fm++)
                    mma16816(acc[fm][fn], aa[fm], bb[fn][0], bb[fn][1]);
        }
        if (c + 1 < NCH){ storeB((c + 1) % NSTAGE, 0); loadB(c + 1, 1); }
        #pragma unroll
        for (int ko = 32; ko < 64; ko += 16){
            uint32_t aa[2][4], bb[8][2];
            const int arow = wm + (lane&15), acol = ko + (lane>>4)*8;
            #pragma unroll
            for (int fm = 0; fm < 2; fm++)
                ldsm4(aa[fm], stA + (uint32_t)((arow + fm*16)*SP + acol)*2);
            const int brw = wn + (lane&7), bcol = ko + ((lane>>3)&1)*8;
            #pragma unroll
            for (int fn = 0; fn < 8; fn++)
                ldsm2(bb[fn], stB + (uint32_t)((brw + fn*8)*SP + bcol)*2);
            #pragma unroll
            for (int fn = 0; fn < 8; fn++)
                #pragma unroll
                for (int fm = 0; fm < 2; fm++)
                    mma16816(acc[fm][fn], aa[fm], bb[fn][0], bb[fn][1]);
        }
        if (c + 1 < NCH) storeB((c + 1) % NSTAGE, 1);
        __syncthreads();
    }

    #pragma unroll
    for (int fm = 0; fm < 2; fm++){
        #pragma unroll
        for (int fn = 0; fn < 8; fn++){
            int row0 = m0 + wm + fm*16 + r;
            int col  = n0 + wn + fn*8 + q*2;
            float2 v0 = make_float2(acc[fm][fn][0], acc[fm][fn][1]);
            float2 v1 = make_float2(acc[fm][fn][2], acc[fm][fn][3]);
            if (do_silu){
                v0.x = silu(v0.x); v0.y = silu(v0.y);
                v1.x = silu(v1.x); v1.y = silu(v1.y);
            }
            *(float2*)(outp + (size_t)row0*HID + col)     = v0;
            *(float2*)(outp + (size_t)(row0+8)*HID + col) = v1;
        }
    }
}

// ---------------- WKV: 512 thr, double-buffered sop, 2 barriers/chunk -------
__global__ __launch_bounds__(512) void wkv_kernel(
    const float* __restrict__ time_decay, const float* __restrict__ time_faaaa)
{
    const int head = blockIdx.x, ehalf = blockIdx.y;
    const int tid = threadIdx.x, eg = tid & 31, dg = tid >> 5;
    __shared__ float ks[16][64], rs[16][64], vs[16][32];
    __shared__ float sop[2][16][16][33];

    float td[4], tf[4], st[4];
    #pragma unroll
    for (int j = 0; j < 4; j++){
        int d = dg*4 + j;
        td[j] = expf(-expf(time_decay[head*HD + d]));
        tf[j] = time_faaaa[head*HD + d];
        st[j] = 0.f;
    }
    const float* kb = g_kvrg + 0*(size_t)SZ + head*HD;
    const float* vb = g_kvrg + 1*(size_t)SZ + head*HD + ehalf*32;
    const float* rb = g_kvrg + 2*(size_t)SZ + head*HD;
    float* op = g_osum + head*HD + ehalf*32;

    const int krow = (tid & 255) >> 4, kseg = tid & 15;
    const int vrow = tid >> 3, vseg = tid & 7;
    float4 kra, va;
    if (tid < 256) kra = *(const float4*)(kb + (size_t)krow*HID + kseg*4);
    else           kra = *(const float4*)(rb + (size_t)krow*HID + kseg*4);
    if (tid < 128) va  = *(const float4*)(vb + (size_t)vrow*HID + vseg*4);

    const int rtt = tid >> 5;
    for (int c = 0; c < SEQ/16; c++){
        const int sb = c & 1;
        if (tid < 256) *(float4*)&ks[krow][kseg*4] = kra;
        else           *(float4*)&rs[krow][kseg*4] = kra;
        if (tid < 128) *(float4*)&vs[vrow][vseg*4] = va;
        __syncthreads();                                  // bar1
        if (c < SEQ/16 - 1){
            const size_t t1 = (size_t)(c+1)*16;
            if (tid < 256) kra = *(const float4*)(kb + (t1+krow)*HID + kseg*4);
            else           kra = *(const float4*)(rb + (t1+krow)*HID + kseg*4);
            if (tid < 128) va  = *(const float4*)(vb + (t1+vrow)*HID + vseg*4);
        }
        #pragma unroll
        for (int tt = 0; tt < 16; tt++){
            const float ve = vs[tt][eg];
            float4 k4 = *(const float4*)&ks[tt][dg*4];
            float4 r4 = *(const float4*)&rs[tt][dg*4];
            float kv, o0, o1;
            kv = k4.x*ve; o0 = r4.x * fmaf(tf[0],kv,st[0]); st[0] = fmaf(td[0],st[0],kv);
            kv = k4.y*ve; o1 = r4.y * fmaf(tf[1],kv,st[1]); st[1] = fmaf(td[1],st[1],kv);
            kv = k4.z*ve; o0 = fmaf(r4.z, fmaf(tf[2],kv,st[2]), o0); st[2] = fmaf(td[2],st[2],kv);
            kv = k4.w*ve; o1 = fmaf(r4.w, fmaf(tf[3],kv,st[3]), o1); st[3] = fmaf(td[3],st[3],kv);
            sop[sb][dg][tt][eg] = o0 + o1;
        }
        __syncthreads();                                  // bar2
        float s = 0.f;
        #pragma unroll
        for (int d2 = 0; d2 < 16; d2++) s += sop[sb][d2][rtt][eg];
        op[(size_t)(c*16 + rtt)*HID + eg] = s;
        // no 3rd barrier: next chunk writes sop[!sb] and restages k/r/v,
        // whose readers all completed at bar2.
    }
}

// ---------------- GroupNorm + gate -> fp16 ----------------------------------
__global__ __launch_bounds__(256) void norm_kernel(
    const float* __restrict__ gnw, const float* __restrict__ gnb)
{
    const int wid = threadIdx.x >> 5, lane = threadIdx.x & 31;
    const int g = blockIdx.x*8 + wid;
    const int t = g >> 6, h = g & 63, e0 = lane*2;
    const size_t bse = (size_t)t*HID + h*HD + e0;

    float2 ov = *(const float2*)(g_osum + bse);
    float o0 = ov.x, o1 = ov.y;
    float s = o0 + o1, s2 = o0*o0 + o1*o1;
    #pragma unroll
    for (int off = 16; off > 0; off >>= 1){
        s  += __shfl_xor_sync(0xffffffffu, s,  off);
        s2 += __shfl_xor_sync(0xffffffffu, s2, off);
    }
    const float mean = s * (1.f/64.f);
    const float var  = s2 * (1.f/64.f) - mean*mean;
    const float rstd = rsqrtf(var + 1e-5f);
    float2 gt = *(const float2*)(g_kvrg + 3*(size_t)SZ + bse);
    const float w0 = gnw[h*HD+e0], w1 = gnw[h*HD+e0+1];
    const float b0 = gnb[h*HD+e0], b1 = gnb[h*HD+e0+1];
    float y0 = ((o0-mean)*rstd*w0 + b0) * gt.x;
    float y1 = ((o1-mean)*rstd*w1 + b1) * gt.y;
    *(uint32_t*)(g_ab + bse) = pkh(__float2half(y0), __float2half(y1));
}

// ---------------------------------------------------------------------------
extern "C" void kernel_launch(void* const* d_in, const int* in_sizes, int n_in,
                              void* d_out, int out_size)
{
    const float* hidden     = (const float*)d_in[0];
    const float* w_key      = (const float*)d_in[1];
    const float* w_value    = (const float*)d_in[2];
    const float* w_recept   = (const float*)d_in[3];
    const float* w_gate     = (const float*)d_in[4];
    const float* w_output   = (const float*)d_in[5];
    const float* tm_key     = (const float*)d_in[6];
    const float* tm_value   = (const float*)d_in[7];
    const float* tm_recept  = (const float*)d_in[8];
    const float* tm_gate    = (const float*)d_in[9];
    const float* time_decay = (const float*)d_in[10];
    const float* time_faaaa = (const float*)d_in[11];
    const float* gn_w       = (const float*)d_in[12];
    const float* gn_b       = (const float*)d_in[13];

    cudaFuncSetAttribute(gemm_kernel, cudaFuncAttributeMaxDynamicSharedMemorySize, GSMEM);

    prepass_kernel<<<SZ/1024, 256>>>(hidden, tm_key, tm_value, tm_recept, tm_gate);

    dim3 gproj(SEQ/128, HID/128, 4);
    gemm_kernel<<<gproj, 256, GSMEM>>>(0, w_key, w_value, w_recept, w_gate,
                                       w_output, nullptr);

    dim3 gwkv(NH, 2);
    wkv_kernel<<<gwkv, 512>>>(time_decay, time_faaaa);

    norm_kernel<<<SEQ*NH/8, 256>>>(gn_w, gn_b);

    dim3 gout(SEQ/128, HID/128, 1);
    gemm_kernel<<<gout, 256, GSMEM>>>(1, w_key, w_value, w_recept, w_gate,
                                      w_output, (float*)d_out);
}

// round 17
// speedup vs baseline: 1.8053x; 1.2614x over previous
#include <cuda_runtime.h>
#include <cuda_fp16.h>
#include <math.h>
#include <stdint.h>

#define SEQ 1024
#define HID 4096
#define NH  64
#define HD  64
#define SZ  (SEQ*HID)
#define SZW (HID*HID)

__device__ float   g_kvrg[4*SZ];     // k,v,r,g fp32
__device__ float   g_osum[SZ];       // WKV output (dgroup-reduced) fp32
__device__ __half  g_mA[4*SZ];       // mixed activations fp16 (RN)
__device__ __half  g_ab[SZ];         // normed/gated fp16
__device__ __half  g_W[5*SZW];       // weights fp16 (k,v,r,g,o)

__device__ __forceinline__ uint32_t pkh(__half a, __half b){
    __half2 t = __halves2half2(a, b);
    return *reinterpret_cast<uint32_t*>(&t);
}
__device__ __forceinline__ float silu(float x){ return x / (1.f + expf(-x)); }
__device__ __forceinline__ uint32_t smem_u32(const void* p){
    uint32_t a;
    asm("{ .reg .u64 t; cvta.to.shared.u64 t, %1; cvt.u32.u64 %0, t; }" : "=r"(a) : "l"(p));
    return a;
}
__device__ __forceinline__ void mma16816(float* c, const uint32_t* a, uint32_t b0, uint32_t b1){
    asm volatile("mma.sync.aligned.m16n8k16.row.col.f32.f16.f16.f32 "
        "{%0,%1,%2,%3}, {%4,%5,%6,%7}, {%8,%9}, {%0,%1,%2,%3};"
        : "+f"(c[0]), "+f"(c[1]), "+f"(c[2]), "+f"(c[3])
        : "r"(a[0]), "r"(a[1]), "r"(a[2]), "r"(a[3]), "r"(b0), "r"(b1));
}
__device__ __forceinline__ void ldsm4(uint32_t* r, uint32_t a){
    asm volatile("ldmatrix.sync.aligned.m8n8.x4.shared.b16 {%0,%1,%2,%3}, [%4];"
        : "=r"(r[0]), "=r"(r[1]), "=r"(r[2]), "=r"(r[3]) : "r"(a));
}
__device__ __forceinline__ void ldsm2(uint32_t* r, uint32_t a){
    asm volatile("ldmatrix.sync.aligned.m8n8.x2.shared.b16 {%0,%1}, [%2];"
        : "=r"(r[0]), "=r"(r[1]) : "r"(a));
}
__device__ __forceinline__ void cpa16(uint32_t dst, const void* src){
    asm volatile("cp.async.cg.shared.global [%0], [%1], 16;" :: "r"(dst), "l"(src));
}
#define CPA_COMMIT() asm volatile("cp.async.commit_group;" ::: "memory")
#define CPA_WAIT1()  asm volatile("cp.async.wait_group 1;" ::: "memory")

// ---------------- weight prepass: fp32 -> fp16 ------------------------------
__global__ __launch_bounds__(256) void prepass_w_kernel(
    const float* __restrict__ wk, const float* __restrict__ wv,
    const float* __restrict__ wr, const float* __restrict__ wg,
    const float* __restrict__ wo)
{
    const int p = blockIdx.y;
    const float* W = (p==0)?wk:(p==1)?wv:(p==2)?wr:(p==3)?wg:wo;
    size_t idx = ((size_t)blockIdx.x*256 + threadIdx.x)*4;
    float4 w4 = *(const float4*)(W + idx);
    *(uint2*)(g_W + (size_t)p*SZW + idx) =
        make_uint2(pkh(__float2half(w4.x), __float2half(w4.y)),
                   pkh(__float2half(w4.z), __float2half(w4.w)));
}

// ---------------- activation prepass: mix -> fp16 (RN) ----------------------
__global__ __launch_bounds__(256) void prepass_kernel(
    const float* __restrict__ hidden, const float* __restrict__ mk,
    const float* __restrict__ mv, const float* __restrict__ mr, const float* __restrict__ mg)
{
    int idx = (blockIdx.x*256 + threadIdx.x)*4;
    int t = idx >> 12, c = idx & 4095;
    float4 hv = *(const float4*)(hidden + idx);
    float4 sv = make_float4(0.f,0.f,0.f,0.f);
    if (t > 0) sv = *(const float4*)(hidden + idx - HID);
    const float* ms[4] = {mk, mv, mr, mg};
    #pragma unroll
    for (int p = 0; p < 4; p++){
        float4 m = *(const float4*)(ms[p] + c);
        float x0 = hv.x*m.x + sv.x*(1.f-m.x), x1 = hv.y*m.y + sv.y*(1.f-m.y);
        float x2 = hv.z*m.z + sv.z*(1.f-m.z), x3 = hv.w*m.w + sv.w*(1.f-m.w);
        *(uint2*)(g_mA + (size_t)p*SZ + idx) =
            make_uint2(pkh(__float2half(x0), __float2half(x1)),
                       pkh(__float2half(x2), __float2half(x3)));
    }
}

// ---------------- mma.sync GEMM, 3-stage cp.async, 2 CTAs/SM ----------------
#define KC 64
#define SP 72
#define TH (128*SP)
#define NSTAGE 3
#define GSMEM (NSTAGE*2*TH*2)

__global__ __launch_bounds__(256, 2) void gemm_kernel(int mode, float* __restrict__ dout)
{
    extern __shared__ __half sm[];
    const int tid = threadIdx.x, z = blockIdx.z;
    const __half *AG, *BG;
    float* outp;
    bool do_silu = false;
    if (mode == 0){
        AG = g_mA + (size_t)z*SZ;
        BG = g_W + (size_t)z*SZW;
        outp = g_kvrg + (size_t)z*SZ; do_silu = (z==3);
    } else {
        AG = g_ab;
        BG = g_W + 4*(size_t)SZW;
        outp = dout;
    }

    const int m0 = blockIdx.x*128, n0 = blockIdx.y*128;
    const int wid = tid>>5, lane = tid&31;
    const int wm = (wid&3)*32, wn = (wid>>2)*64;
    const int r = lane>>2, q = lane&3;
    const uint32_t sbase = smem_u32(sm);

    const int crow = tid>>3, cseg = tid&7;
    const size_t gAoff = (size_t)(m0+crow)*HID + cseg*8;
    const size_t gBoff = (size_t)(n0+crow)*HID + cseg*8;
    const uint32_t soff = (uint32_t)(crow*SP + cseg*8)*2;

    float acc[2][8][4];
    #pragma unroll
    for (int i=0;i<2;i++)
        #pragma unroll
        for (int j=0;j<8;j++)
            #pragma unroll
            for (int k=0;k<4;k++) acc[i][j][k]=0.f;

    auto issue = [&](int c, int s){
        const int k0 = c*KC;
        const uint32_t st = sbase + (uint32_t)(s*2*TH)*2;
        #pragma unroll
        for (int i = 0; i < 4; i++){
            const uint32_t dof = soff + (uint32_t)(i*32*SP)*2;
            cpa16(st + dof,                  AG + gAoff + k0 + (size_t)i*32*HID);
            cpa16(st + (uint32_t)TH*2 + dof, BG + gBoff + k0 + (size_t)i*32*HID);
        }
    };

    issue(0, 0); CPA_COMMIT();
    issue(1, 1); CPA_COMMIT();

    const int NCH = HID/KC;
    for (int c = 0; c < NCH; c++){
        const int s = c % NSTAGE;
        CPA_WAIT1();
        __syncthreads();
        if (c + 2 < NCH) issue(c + 2, (c + 2) % NSTAGE);
        CPA_COMMIT();

        const uint32_t stA = sbase + (uint32_t)(s*2*TH)*2;
        const uint32_t stB = stA + (uint32_t)TH*2;

        #pragma unroll
        for (int ko = 0; ko < KC; ko += 16){
            uint32_t aa[2][4], bb[8][2];
            const int arow = wm + (lane&15), acol = ko + (lane>>4)*8;
            #pragma unroll
            for (int fm = 0; fm < 2; fm++)
                ldsm4(aa[fm], stA + (uint32_t)((arow + fm*16)*SP + acol)*2);
            const int brw = wn + (lane&7), bcol = ko + ((lane>>3)&1)*8;
            #pragma unroll
            for (int fn = 0; fn < 8; fn++)
                ldsm2(bb[fn], stB + (uint32_t)((brw + fn*8)*SP + bcol)*2);
            #pragma unroll
            for (int fn = 0; fn < 8; fn++)
                #pragma unroll
                for (int fm = 0; fm < 2; fm++)
                    mma16816(acc[fm][fn], aa[fm], bb[fn][0], bb[fn][1]);
        }
        __syncthreads();
    }

    #pragma unroll
    for (int fm = 0; fm < 2; fm++){
        #pragma unroll
        for (int fn = 0; fn < 8; fn++){
            int row0 = m0 + wm + fm*16 + r;
            int col  = n0 + wn + fn*8 + q*2;
            float2 v0 = make_float2(acc[fm][fn][0], acc[fm][fn][1]);
            float2 v1 = make_float2(acc[fm][fn][2], acc[fm][fn][3]);
            if (do_silu){
                v0.x = silu(v0.x); v0.y = silu(v0.y);
                v1.x = silu(v1.x); v1.y = silu(v1.y);
            }
            *(float2*)(outp + (size_t)row0*HID + col)     = v0;
            *(float2*)(outp + (size_t)(row0+8)*HID + col) = v1;
        }
    }
}

// ---------------- WKV: 512 thr, double-buffered sop, 2 barriers/chunk -------
__global__ __launch_bounds__(512) void wkv_kernel(
    const float* __restrict__ time_decay, const float* __restrict__ time_faaaa)
{
    const int head = blockIdx.x, ehalf = blockIdx.y;
    const int tid = threadIdx.x, eg = tid & 31, dg = tid >> 5;
    __shared__ float ks[16][64], rs[16][64], vs[16][32];
    __shared__ float sop[2][16][16][33];

    float td[4], tf[4], st[4];
    #pragma unroll
    for (int j = 0; j < 4; j++){
        int d = dg*4 + j;
        td[j] = expf(-expf(time_decay[head*HD + d]));
        tf[j] = time_faaaa[head*HD + d];
        st[j] = 0.f;
    }
    const float* kb = g_kvrg + 0*(size_t)SZ + head*HD;
    const float* vb = g_kvrg + 1*(size_t)SZ + head*HD + ehalf*32;
    const float* rb = g_kvrg + 2*(size_t)SZ + head*HD;
    float* op = g_osum + head*HD + ehalf*32;

    const int krow = (tid & 255) >> 4, kseg = tid & 15;
    const int vrow = tid >> 3, vseg = tid & 7;
    float4 kra, va;
    if (tid < 256) kra = *(const float4*)(kb + (size_t)krow*HID + kseg*4);
    else           kra = *(const float4*)(rb + (size_t)krow*HID + kseg*4);
    if (tid < 128) va  = *(const float4*)(vb + (size_t)vrow*HID + vseg*4);

    const int rtt = tid >> 5;
    for (int c = 0; c < SEQ/16; c++){
        const int sb = c & 1;
        if (tid < 256) *(float4*)&ks[krow][kseg*4] = kra;
        else           *(float4*)&rs[krow][kseg*4] = kra;
        if (tid < 128) *(float4*)&vs[vrow][vseg*4] = va;
        __syncthreads();                                  // bar1
        if (c < SEQ/16 - 1){
            const size_t t1 = (size_t)(c+1)*16;
            if (tid < 256) kra = *(const float4*)(kb + (t1+krow)*HID + kseg*4);
            else           kra = *(const float4*)(rb + (t1+krow)*HID + kseg*4);
            if (tid < 128) va  = *(const float4*)(vb + (t1+vrow)*HID + vseg*4);
        }
        #pragma unroll
        for (int tt = 0; tt < 16; tt++){
            const float ve = vs[tt][eg];
            float4 k4 = *(const float4*)&ks[tt][dg*4];
            float4 r4 = *(const float4*)&rs[tt][dg*4];
            float kv, o0, o1;
            kv = k4.x*ve; o0 = r4.x * fmaf(tf[0],kv,st[0]); st[0] = fmaf(td[0],st[0],kv);
            kv = k4.y*ve; o1 = r4.y * fmaf(tf[1],kv,st[1]); st[1] = fmaf(td[1],st[1],kv);
            kv = k4.z*ve; o0 = fmaf(r4.z, fmaf(tf[2],kv,st[2]), o0); st[2] = fmaf(td[2],st[2],kv);
            kv = k4.w*ve; o1 = fmaf(r4.w, fmaf(tf[3],kv,st[3]), o1); st[3] = fmaf(td[3],st[3],kv);
            sop[sb][dg][tt][eg] = o0 + o1;
        }
        __syncthreads();                                  // bar2
        float s = 0.f;
        #pragma unroll
        for (int d2 = 0; d2 < 16; d2++) s += sop[sb][d2][rtt][eg];
        op[(size_t)(c*16 + rtt)*HID + eg] = s;
        // no 3rd barrier: next chunk writes sop[!sb]; k/r/v restage readers
        // all completed at bar2.
    }
}

// ---------------- GroupNorm + gate -> fp16 ----------------------------------
__global__ __launch_bounds__(256) void norm_kernel(
    const float* __restrict__ gnw, const float* __restrict__ gnb)
{
    const int wid = threadIdx.x >> 5, lane = threadIdx.x & 31;
    const int g = blockIdx.x*8 + wid;
    const int t = g >> 6, h = g & 63, e0 = lane*2;
    const size_t bse = (size_t)t*HID + h*HD + e0;

    float2 ov = *(const float2*)(g_osum + bse);
    float o0 = ov.x, o1 = ov.y;
    float s = o0 + o1, s2 = o0*o0 + o1*o1;
    #pragma unroll
    for (int off = 16; off > 0; off >>= 1){
        s  += __shfl_xor_sync(0xffffffffu, s,  off);
        s2 += __shfl_xor_sync(0xffffffffu, s2, off);
    }
    const float mean = s * (1.f/64.f);
    const float var  = s2 * (1.f/64.f) - mean*mean;
    const float rstd = rsqrtf(var + 1e-5f);
    float2 gt = *(const float2*)(g_kvrg + 3*(size_t)SZ + bse);
    const float w0 = gnw[h*HD+e0], w1 = gnw[h*HD+e0+1];
    const float b0 = gnb[h*HD+e0], b1 = gnb[h*HD+e0+1];
    float y0 = ((o0-mean)*rstd*w0 + b0) * gt.x;
    float y1 = ((o1-mean)*rstd*w1 + b1) * gt.y;
    *(uint32_t*)(g_ab + bse) = pkh(__float2half(y0), __float2half(y1));
}

// ---------------------------------------------------------------------------
extern "C" void kernel_launch(void* const* d_in, const int* in_sizes, int n_in,
                              void* d_out, int out_size)
{
    const float* hidden     = (const float*)d_in[0];
    const float* w_key      = (const float*)d_in[1];
    const float* w_value    = (const float*)d_in[2];
    const float* w_recept   = (const float*)d_in[3];
    const float* w_gate     = (const float*)d_in[4];
    const float* w_output   = (const float*)d_in[5];
    const float* tm_key     = (const float*)d_in[6];
    const float* tm_value   = (const float*)d_in[7];
    const float* tm_recept  = (const float*)d_in[8];
    const float* tm_gate    = (const float*)d_in[9];
    const float* time_decay = (const float*)d_in[10];
    const float* time_faaaa = (const float*)d_in[11];
    const float* gn_w       = (const float*)d_in[12];
    const float* gn_b       = (const float*)d_in[13];

    cudaFuncSetAttribute(gemm_kernel, cudaFuncAttributeMaxDynamicSharedMemorySize, GSMEM);

    dim3 gw(SZW/1024, 5);
    prepass_w_kernel<<<gw, 256>>>(w_key, w_value, w_recept, w_gate, w_output);
    prepass_kernel<<<SZ/1024, 256>>>(hidden, tm_key, tm_value, tm_recept, tm_gate);

    dim3 gproj(SEQ/128, HID/128, 4);
    gemm_kernel<<<gproj, 256, GSMEM>>>(0, nullptr);

    dim3 gwkv(NH, 2);
    wkv_kernel<<<gwkv, 512>>>(time_decay, time_faaaa);

    norm_kernel<<<SEQ*NH/8, 256>>>(gn_w, gn_b);

    dim3 gout(SEQ/128, HID/128, 1);
    gemm_kernel<<<gout, 256, GSMEM>>>(1, (float*)d_out);
}